// round 6
// baseline (speedup 1.0000x reference)
#include <cuda_runtime.h>
#include <cuda_fp16.h>
#include <cstddef>

#define NN   50000
#define FI   128
#define HC   128
#define NH   4
#define EMAX 1600000
#define EAMAX (EMAX + NN)

// ---------------- scratch (device globals; no allocations) ----------------
__device__ alignas(16) __half g_xw1h[(size_t)NN * HC]; // 12.8 MB (fp16 messages)
__device__ alignas(16) float  g_asrc1[NN * NH];
__device__ alignas(16) float  g_adst1[NN * NH];
__device__ alignas(16) float  g_xw2[NN];
__device__ int g_deg[NN];
__device__ int g_off[NN + 1];
__device__ int g_cur[NN];
__device__ int g_csr[EAMAX];
__device__ int g_is64;

// ---------------- helpers ----------------
__device__ __forceinline__ float lrelu(float v) { return v > 0.f ? v : 0.2f * v; }

__device__ __forceinline__ float warp_sum(float v) {
#pragma unroll
    for (int o = 16; o; o >>= 1) v += __shfl_down_sync(0xffffffffu, v, o);
    return v;
}

// ---------------- edge-index dtype detect ----------------
__global__ void k_detect(const int* __restrict__ ei32) {
    if (threadIdx.x == 0) {
        int is64 = 1;
        for (int i = 0; i < 64; i++)
            if (ei32[2 * i + 1] != 0) { is64 = 0; break; }
        g_is64 = is64;
    }
}

__device__ __forceinline__ int load_idx(const void* ei, int pos) {
    return g_is64 ? (int)((const long long*)ei)[pos] : ((const int*)ei)[pos];
}

// ---------------- CSR build: count / scan / fill ----------------
__global__ void k_count(const void* __restrict__ ei, int E, int EA) {
    int e = blockIdx.x * blockDim.x + threadIdx.x;
    if (e >= EA) return;
    int dst = (e < E) ? load_idx(ei, E + e) : (e - E);
    atomicAdd(&g_deg[dst], 1);
}

__global__ void k_scan(int N, int EA) {
    __shared__ int part[1024];
    int t = threadIdx.x;
    int chunk = (N + 1023) / 1024;
    int s0 = t * chunk, s1 = min(s0 + chunk, N);
    int s = 0;
    for (int i = s0; i < s1; i++) s += g_deg[i];
    part[t] = s;
    __syncthreads();
    for (int o = 1; o < 1024; o <<= 1) {
        int v = (t >= o) ? part[t - o] : 0;
        __syncthreads();
        part[t] += v;
        __syncthreads();
    }
    int run = t ? part[t - 1] : 0;
    for (int i = s0; i < s1; i++) {
        g_off[i] = run;
        g_cur[i] = run;
        run += g_deg[i];
    }
    if (t == 1023) g_off[N] = EA;
}

__global__ void k_fill(const void* __restrict__ ei, int E, int EA) {
    int e = blockIdx.x * blockDim.x + threadIdx.x;
    if (e >= EA) return;
    int src, dst;
    if (e < E) { src = load_idx(ei, e); dst = load_idx(ei, E + e); }
    else       { src = dst = e - E; }
    int p = atomicAdd(&g_cur[dst], 1);
    g_csr[p] = src;
}

// ---------------- layer 1 GEMM + fused attention logits, fp16 store ----------------
#define GEMM_SMEM ((128 * 129 + 32 * 128) * 4)
__global__ void k_gemm1(const float* __restrict__ x, const float* __restrict__ W1,
                        const float* __restrict__ as1, const float* __restrict__ ad1,
                        int N) {
    extern __shared__ float sm[];
    float* Wt = sm;                 // [k*129 + j]
    float* xs = sm + 128 * 129;     // [m*128 + k]
    int tid = threadIdx.x;
    for (int idx = tid; idx < HC * FI; idx += 256) {
        int j = idx >> 7, k = idx & 127;
        Wt[k * 129 + j] = W1[idx];
    }
    int nb = blockIdx.x * 32;
    for (int idx = tid; idx < 32 * FI; idx += 256) {
        int m = idx >> 7;
        int n = nb + m;
        xs[idx] = (n < N) ? x[(size_t)n * FI + (idx & 127)] : 0.f;
    }
    __syncthreads();
    int j = tid & 127, mh = tid >> 7;
    float acc[16];
#pragma unroll
    for (int i = 0; i < 16; i++) acc[i] = 0.f;
    for (int k = 0; k < FI; k += 4) {
        float w0 = Wt[(k + 0) * 129 + j];
        float w1 = Wt[(k + 1) * 129 + j];
        float w2 = Wt[(k + 2) * 129 + j];
        float w3 = Wt[(k + 3) * 129 + j];
#pragma unroll
        for (int i = 0; i < 16; i++) {
            float4 xv = *(const float4*)&xs[(mh * 16 + i) * FI + k];
            acc[i] += xv.x * w0 + xv.y * w1 + xv.z * w2 + xv.w * w3;
        }
    }
    // store xw1 (fp16)
#pragma unroll
    for (int i = 0; i < 16; i++) {
        int n = nb + mh * 16 + i;
        if (n < N) g_xw1h[(size_t)n * HC + j] = __float2half(acc[i]);
    }
    // fused attention logits (fp32, exact): this warp covers exactly head h
    int l = tid & 31;
    int h = (tid >> 5) & 3;
    float av = as1[j];
    float dv = ad1[j];
#pragma unroll
    for (int i = 0; i < 16; i++) {
        float s = warp_sum(acc[i] * av);
        float d = warp_sum(acc[i] * dv);
        int n = nb + mh * 16 + i;
        if (l == 0 && n < N) {
            g_asrc1[n * NH + h] = s;
            g_adst1[n * NH + h] = d;
        }
    }
}

// ---------------- layer-1 fused: softmax-gather + bias + ReLU + GEMV ----------------
// warp per dst node; lane l covers cols 4l..4l+3 (head h=l>>3); fp16 rows, 2x unroll.
__device__ __forceinline__ void acc_row(int src, float adh, int h, int l,
                                        float& ax, float& ay, float& az, float& aw,
                                        float& den) {
    float a = g_asrc1[src * NH + h] + adh;
    float ex = __expf(lrelu(a));
    den += ex;
    uint2 u = *(const uint2*)&g_xw1h[(size_t)src * HC + 4 * l];
    __half2 h0 = *(__half2*)&u.x;
    __half2 h1 = *(__half2*)&u.y;
    float2 f0 = __half22float2(h0);
    float2 f1 = __half22float2(h1);
    ax += ex * f0.x; ay += ex * f0.y; az += ex * f1.x; aw += ex * f1.y;
}

__global__ void k_l1(const float* __restrict__ b1, const float* __restrict__ W2, int N) {
    int n = (blockIdx.x * blockDim.x + threadIdx.x) >> 5;
    if (n >= N) return;
    int l = threadIdx.x & 31;
    int h = l >> 3;
    int beg = g_off[n], end = g_off[n + 1];
    float adh = g_adst1[n * NH + h];
    float ax = 0.f, ay = 0.f, az = 0.f, aw = 0.f, den = 0.f;
    float bx = 0.f, by = 0.f, bz = 0.f, bw = 0.f, den2 = 0.f;
    int e = beg;
    for (; e + 1 < end; e += 2) {
        int s0 = g_csr[e];
        int s1 = g_csr[e + 1];
        acc_row(s0, adh, h, l, ax, ay, az, aw, den);
        acc_row(s1, adh, h, l, bx, by, bz, bw, den2);
    }
    if (e < end) {
        int s0 = g_csr[e];
        acc_row(s0, adh, h, l, ax, ay, az, aw, den);
    }
    ax += bx; ay += by; az += bz; aw += bw; den += den2;
    float inv = 1.f / (den + 1e-16f);
    float4 bb = *(const float4*)&b1[4 * l];
    float4 ww = *(const float4*)&W2[4 * l];
    float s = fmaxf(ax * inv + bb.x, 0.f) * ww.x
            + fmaxf(ay * inv + bb.y, 0.f) * ww.y
            + fmaxf(az * inv + bb.z, 0.f) * ww.z
            + fmaxf(aw * inv + bb.w, 0.f) * ww.w;
    s = warp_sum(s);
    if (l == 0) g_xw2[n] = s;
}

// ---------------- layer-2 fused: softmax-gather + bias -> d_out ----------------
__global__ void k_l2(const float* __restrict__ as2, const float* __restrict__ ad2,
                     const float* __restrict__ b2, float* __restrict__ out, int N) {
    int n = (blockIdx.x * blockDim.x + threadIdx.x) >> 5;
    if (n >= N) return;
    int l = threadIdx.x & 31;
    int beg = g_off[n], end = g_off[n + 1];
    float xd = g_xw2[n] * ad2[0];
    float asc = as2[0];
    float den = 0.f, num = 0.f;
    for (int e = beg + l; e < end; e += 32) {
        float xs = g_xw2[g_csr[e]];
        float ex = __expf(lrelu(xs * asc + xd));
        den += ex;
        num += ex * xs;
    }
    den = warp_sum(den);
    num = warp_sum(num);
    if (l == 0) out[n] = num / (den + 1e-16f) + b2[0];
}

// ---------------- launch ----------------
extern "C" void kernel_launch(void* const* d_in, const int* in_sizes, int n_in,
                              void* d_out, int out_size) {
    const float* x   = (const float*)d_in[0];
    const void*  ei  = d_in[1];
    const float* W1  = (const float*)d_in[2];
    const float* as1 = (const float*)d_in[3];
    const float* ad1 = (const float*)d_in[4];
    const float* b1  = (const float*)d_in[5];
    const float* W2  = (const float*)d_in[6];
    const float* as2 = (const float*)d_in[7];
    const float* ad2 = (const float*)d_in[8];
    const float* b2  = (const float*)d_in[9];

    int N  = in_sizes[0] / FI;
    int E  = in_sizes[1] / 2;
    int EA = E + N;

    static cudaStream_t s_csr = nullptr;
    static cudaEvent_t ev_fork = nullptr, ev_join = nullptr;
    if (!s_csr) {
        cudaStreamCreateWithFlags(&s_csr, cudaStreamNonBlocking);
        cudaEventCreateWithFlags(&ev_fork, cudaEventDisableTiming);
        cudaEventCreateWithFlags(&ev_join, cudaEventDisableTiming);
    }

    void* pdeg;
    cudaGetSymbolAddress(&pdeg, g_deg);
    cudaMemsetAsync(pdeg, 0, (size_t)N * sizeof(int), 0);

    cudaFuncSetAttribute(k_gemm1, cudaFuncAttributeMaxDynamicSharedMemorySize, GEMM_SMEM);

    // fork: CSR build on side stream
    cudaEventRecord(ev_fork, 0);
    cudaStreamWaitEvent(s_csr, ev_fork, 0);
    int eb = (EA + 255) / 256;
    k_detect<<<1, 32, 0, s_csr>>>((const int*)ei);
    k_count<<<eb, 256, 0, s_csr>>>(ei, E, EA);
    k_scan<<<1, 1024, 0, s_csr>>>(N, EA);
    k_fill<<<eb, 256, 0, s_csr>>>(ei, E, EA);
    cudaEventRecord(ev_join, s_csr);

    // main stream: GEMM (+ fused attention logits)
    k_gemm1<<<(N + 31) / 32, 256, GEMM_SMEM>>>(x, W1, as1, ad1, N);

    // join, then fused layers
    cudaStreamWaitEvent(0, ev_join, 0);
    k_l1<<<((size_t)N * 32 + 255) / 256, 256>>>(b1, W2, N);
    k_l2<<<((size_t)N * 32 + 255) / 256, 256>>>(as2, ad2, b2, (float*)d_out, N);
}

// round 8
// speedup vs baseline: 1.4391x; 1.4391x over previous
#include <cuda_runtime.h>
#include <cuda_fp16.h>
#include <cstddef>

#define NN   50000
#define FI   128
#define HC   128
#define NH   4
#define EMAX 1600000
#define EAMAX (EMAX + NN)

// ---------------- scratch (device globals; no allocations) ----------------
__device__ alignas(16) __half g_xw1h[(size_t)NN * HC]; // 12.8 MB fp16 messages
__device__ alignas(16) float  g_asrc1[NN * NH];
__device__ alignas(16) float  g_adst1[NN * NH];
__device__ alignas(16) float  g_xw2[NN];
__device__ int g_deg[NN];
__device__ int g_off[NN + 1];
__device__ int g_cur[NN];
__device__ int g_csr[EAMAX];
__device__ int g_is64;

// ---------------- helpers ----------------
__device__ __forceinline__ float lrelu(float v) { return v > 0.f ? v : 0.2f * v; }

__device__ __forceinline__ float warp_sum(float v) {
#pragma unroll
    for (int o = 16; o; o >>= 1) v += __shfl_down_sync(0xffffffffu, v, o);
    return v;
}

// ---------------- init: zero g_deg + dtype detect (one kernel, one launch) ----------------
__global__ void k_init(const int* __restrict__ ei32, int N) {
    int i = blockIdx.x * blockDim.x + threadIdx.x;
    if (i < N) g_deg[i] = 0;
    if (i == 0) {
        int is64 = 1;
        for (int k = 0; k < 64; k++)
            if (ei32[2 * k + 1] != 0) { is64 = 0; break; }
        g_is64 = is64;
    }
}

__device__ __forceinline__ int load_idx(const void* ei, int pos) {
    return g_is64 ? (int)((const long long*)ei)[pos] : ((const int*)ei)[pos];
}

// ---------------- CSR build: count / scan / fill ----------------
__global__ void k_count(const void* __restrict__ ei, int E, int EA) {
    int e = blockIdx.x * blockDim.x + threadIdx.x;
    if (e >= EA) return;
    int dst = (e < E) ? load_idx(ei, E + e) : (e - E);
    atomicAdd(&g_deg[dst], 1);
}

__global__ void k_scan(int N, int EA) {
    __shared__ int part[1024];
    int t = threadIdx.x;
    int chunk = (N + 1023) / 1024;
    int s0 = t * chunk, s1 = min(s0 + chunk, N);
    int s = 0;
    for (int i = s0; i < s1; i++) s += g_deg[i];
    part[t] = s;
    __syncthreads();
    for (int o = 1; o < 1024; o <<= 1) {
        int v = (t >= o) ? part[t - o] : 0;
        __syncthreads();
        part[t] += v;
        __syncthreads();
    }
    int run = t ? part[t - 1] : 0;
    for (int i = s0; i < s1; i++) {
        g_off[i] = run;
        g_cur[i] = run;
        run += g_deg[i];
    }
    if (t == 1023) g_off[N] = EA;
}

__global__ void k_fill(const void* __restrict__ ei, int E, int EA) {
    int e = blockIdx.x * blockDim.x + threadIdx.x;
    if (e >= EA) return;
    int src, dst;
    if (e < E) { src = load_idx(ei, e); dst = load_idx(ei, E + e); }
    else       { src = dst = e - E; }
    int p = atomicAdd(&g_cur[dst], 1);
    g_csr[p] = src;
}

// ---------------- layer 1 GEMM + fused attention logits, fp16 store ----------------
#define GEMM_SMEM ((128 * 129 + 32 * 128) * 4)
__global__ void k_gemm1(const float* __restrict__ x, const float* __restrict__ W1,
                        const float* __restrict__ as1, const float* __restrict__ ad1,
                        int N) {
    extern __shared__ float sm[];
    float* Wt = sm;                 // [k*129 + j]
    float* xs = sm + 128 * 129;     // [m*128 + k]
    int tid = threadIdx.x;
    for (int idx = tid; idx < HC * FI; idx += 256) {
        int j = idx >> 7, k = idx & 127;
        Wt[k * 129 + j] = W1[idx];
    }
    int nb = blockIdx.x * 32;
    for (int idx = tid; idx < 32 * FI; idx += 256) {
        int m = idx >> 7;
        int n = nb + m;
        xs[idx] = (n < N) ? x[(size_t)n * FI + (idx & 127)] : 0.f;
    }
    __syncthreads();
    int j = tid & 127, mh = tid >> 7;
    float acc[16];
#pragma unroll
    for (int i = 0; i < 16; i++) acc[i] = 0.f;
    for (int k = 0; k < FI; k += 4) {
        float w0 = Wt[(k + 0) * 129 + j];
        float w1 = Wt[(k + 1) * 129 + j];
        float w2 = Wt[(k + 2) * 129 + j];
        float w3 = Wt[(k + 3) * 129 + j];
#pragma unroll
        for (int i = 0; i < 16; i++) {
            float4 xv = *(const float4*)&xs[(mh * 16 + i) * FI + k];
            acc[i] += xv.x * w0 + xv.y * w1 + xv.z * w2 + xv.w * w3;
        }
    }
    // store xw1 (fp16)
#pragma unroll
    for (int i = 0; i < 16; i++) {
        int n = nb + mh * 16 + i;
        if (n < N) g_xw1h[(size_t)n * HC + j] = __float2half(acc[i]);
    }
    // fused attention logits (fp32, exact): warp covers exactly head h
    int l = tid & 31;
    int h = (tid >> 5) & 3;
    float av = as1[j];
    float dv = ad1[j];
#pragma unroll
    for (int i = 0; i < 16; i++) {
        float s = warp_sum(acc[i] * av);
        float d = warp_sum(acc[i] * dv);
        int n = nb + mh * 16 + i;
        if (l == 0 && n < N) {
            g_asrc1[n * NH + h] = s;
            g_adst1[n * NH + h] = d;
        }
    }
}

// ---------------- layer-1 fused: softmax-gather + bias + ReLU + GEMV ----------------
// warp per dst node; lane l covers cols 4l..4l+3 (head h=l>>3).
// Single dependent chain (round-5 structure), fp16 rows.
__global__ void __launch_bounds__(256) k_l1(const float* __restrict__ b1,
                                            const float* __restrict__ W2, int N) {
    int n = (blockIdx.x * blockDim.x + threadIdx.x) >> 5;
    if (n >= N) return;
    int l = threadIdx.x & 31;
    int h = l >> 3;
    int beg = g_off[n], end = g_off[n + 1];
    float adh = g_adst1[n * NH + h];
    float ax = 0.f, ay = 0.f, az = 0.f, aw = 0.f, den = 0.f;
    for (int e = beg; e < end; e++) {
        int src = g_csr[e];
        float a = g_asrc1[src * NH + h] + adh;
        float ex = __expf(lrelu(a));
        den += ex;
        uint2 u = *(const uint2*)&g_xw1h[(size_t)src * HC + 4 * l];
        float2 f0 = __half22float2(*(__half2*)&u.x);
        float2 f1 = __half22float2(*(__half2*)&u.y);
        ax += ex * f0.x; ay += ex * f0.y; az += ex * f1.x; aw += ex * f1.y;
    }
    float inv = 1.f / (den + 1e-16f);
    float4 bb = *(const float4*)&b1[4 * l];
    float4 ww = *(const float4*)&W2[4 * l];
    float s = fmaxf(ax * inv + bb.x, 0.f) * ww.x
            + fmaxf(ay * inv + bb.y, 0.f) * ww.y
            + fmaxf(az * inv + bb.z, 0.f) * ww.z
            + fmaxf(aw * inv + bb.w, 0.f) * ww.w;
    s = warp_sum(s);
    if (l == 0) g_xw2[n] = s;
}

// ---------------- layer-2 fused: softmax-gather + bias -> d_out ----------------
__global__ void k_l2(const float* __restrict__ as2, const float* __restrict__ ad2,
                     const float* __restrict__ b2, float* __restrict__ out, int N) {
    int n = (blockIdx.x * blockDim.x + threadIdx.x) >> 5;
    if (n >= N) return;
    int l = threadIdx.x & 31;
    int beg = g_off[n], end = g_off[n + 1];
    float xd = g_xw2[n] * ad2[0];
    float asc = as2[0];
    float den = 0.f, num = 0.f;
    for (int e = beg + l; e < end; e += 32) {
        float xs = g_xw2[g_csr[e]];
        float ex = __expf(lrelu(xs * asc + xd));
        den += ex;
        num += ex * xs;
    }
    den = warp_sum(den);
    num = warp_sum(num);
    if (l == 0) out[n] = num / (den + 1e-16f) + b2[0];
}

// ---------------- launch ----------------
extern "C" void kernel_launch(void* const* d_in, const int* in_sizes, int n_in,
                              void* d_out, int out_size) {
    const float* x   = (const float*)d_in[0];
    const void*  ei  = d_in[1];
    const float* W1  = (const float*)d_in[2];
    const float* as1 = (const float*)d_in[3];
    const float* ad1 = (const float*)d_in[4];
    const float* b1  = (const float*)d_in[5];
    const float* W2  = (const float*)d_in[6];
    const float* as2 = (const float*)d_in[7];
    const float* ad2 = (const float*)d_in[8];
    const float* b2  = (const float*)d_in[9];

    int N  = in_sizes[0] / FI;
    int E  = in_sizes[1] / 2;
    int EA = E + N;

    static cudaStream_t s_csr = nullptr;
    static cudaEvent_t ev_fork = nullptr, ev_join = nullptr;
    if (!s_csr) {
        cudaStreamCreateWithFlags(&s_csr, cudaStreamNonBlocking);
        cudaEventCreateWithFlags(&ev_fork, cudaEventDisableTiming);
        cudaEventCreateWithFlags(&ev_join, cudaEventDisableTiming);
    }

    cudaFuncSetAttribute(k_gemm1, cudaFuncAttributeMaxDynamicSharedMemorySize, GEMM_SMEM);

    // fork: CSR build on side stream (init also zeroes g_deg)
    cudaEventRecord(ev_fork, 0);
    cudaStreamWaitEvent(s_csr, ev_fork, 0);
    int eb = (EA + 255) / 256;
    k_init<<<(NN + 255) / 256, 256, 0, s_csr>>>((const int*)ei, N);
    k_count<<<eb, 256, 0, s_csr>>>(ei, E, EA);
    k_scan<<<1, 1024, 0, s_csr>>>(N, EA);
    k_fill<<<eb, 256, 0, s_csr>>>(ei, E, EA);
    cudaEventRecord(ev_join, s_csr);

    // main stream: GEMM (+ fused attention logits)
    k_gemm1<<<(N + 31) / 32, 256, GEMM_SMEM>>>(x, W1, as1, ad1, N);

    // join, then fused layers
    cudaStreamWaitEvent(0, ev_join, 0);
    k_l1<<<((size_t)N * 32 + 255) / 256, 256>>>(b1, W2, N);
    k_l2<<<((size_t)N * 32 + 255) / 256, 256>>>(as2, ad2, b2, (float*)d_out, N);
}